// round 9
// baseline (speedup 1.0000x reference)
#include <cuda_runtime.h>
#include <math.h>
#include <stdint.h>

// ---------------------------------------------------------------------------
// AttSRU: T=512, B=32, S=512, D=512, fp32.
// Round 9: 256x128 GEMM CTA tiles (0.75x L2 operand traffic, half the CTAs).
// 512 threads / 16 warps, same 32x64 warp tile, 3-stage cp.async pipeline.
// ---------------------------------------------------------------------------

namespace {
constexpr int  kT = 512, kB = 32, kS = 512, kD = 512;
constexpr long kTB   = (long)kT * kB;      // 16384 rows
constexpr long kTBD  = kTB * kD;           // 8388608
constexpr long kPRE  = kTB * 3 * kD;       // 25165824
constexpr float kEPS = 1e-6f;

// scratch layout (single __device__ array)
constexpr long OF_PRE   = 0;                 // [TB, 3D] raw preact
constexpr long OF_Z     = kPRE;              // [T,B,D] sigmoid(z)
constexpr long OF_HG    = OF_Z    + kTBD;    // [T,B,D] sigmoid(h_gate)
constexpr long OF_PL    = OF_HG   + kTBD;    // [T,B,D] pl_t
constexpr long OF_PCTX  = OF_PL   + kTBD;    // [B,S,D] LN(enc@W_enc)
constexpr long OF_SS    = OF_PCTX + kTBD;    // [T,B,D] scan states
constexpr long OF_ATT   = OF_SS   + kTBD;    // [T,B,D] LN(ss@W_attn)
constexpr long OF_AV    = OF_ATT  + kTBD;    // [B,T,S] align -> softmax
constexpr long OF_AO    = OF_AV   + kTBD;    // [T,B,D] attn_out
constexpr long OF_H1    = OF_AO   + kTBD;    // [TB,D]
constexpr long OF_H2    = OF_H1   + kTBD;    // [TB,D]
constexpr long OF_PCTXT = OF_H2   + kTBD;    // [B,D,S] pctx transposed
constexpr long OF_WTIN  = OF_PCTXT + kTBD;   // [3D,D]
constexpr long OF_WTENC = OF_WTIN  + (long)3 * kD * kD;
constexpr long OF_WTATT = OF_WTENC + (long)kD * kD;
constexpr long OF_WTHID = OF_WTATT + (long)kD * kD;
constexpr long OF_WTCTX = OF_WTHID + (long)kD * kD;
constexpr long kSCRATCH = OF_WTCTX + (long)kD * kD;

// GEMM: CTA tile 256x128, K-chunk 32; smem row stride 36 floats
constexpr int RS = 36;                        // floats per smem row
constexpr int A_ROWS = 256, B_ROWS = 128;
constexpr int OP_A = A_ROWS * RS;             // A floats per stage
constexpr int STAGE_FLOATS = (A_ROWS + B_ROWS) * RS;
constexpr int GEMM_SMEM = 3 * STAGE_FLOATS * 4;   // 165888 B
}

__device__ float g_scratch[kSCRATCH];

// ---------------------------------------------------------------------------
// Helpers
// ---------------------------------------------------------------------------
__device__ __forceinline__ float warpSum(float v) {
#pragma unroll
    for (int o = 16; o; o >>= 1) v += __shfl_xor_sync(0xffffffffu, v, o);
    return v;
}
__device__ __forceinline__ float warpMax(float v) {
#pragma unroll
    for (int o = 16; o; o >>= 1) v = fmaxf(v, __shfl_xor_sync(0xffffffffu, v, o));
    return v;
}
__device__ __forceinline__ float blockSum(float v, float* sh) {
    int w = threadIdx.x >> 5, l = threadIdx.x & 31, nw = blockDim.x >> 5;
    v = warpSum(v);
    if (l == 0) sh[w] = v;
    __syncthreads();
    v = (l < nw) ? sh[l] : 0.f;
    v = warpSum(v);
    __syncthreads();
    return v;
}
__device__ __forceinline__ float blockMax(float v, float* sh) {
    int w = threadIdx.x >> 5, l = threadIdx.x & 31, nw = blockDim.x >> 5;
    v = warpMax(v);
    if (l == 0) sh[w] = v;
    __syncthreads();
    v = (l < nw) ? sh[l] : -INFINITY;
    v = warpMax(v);
    __syncthreads();
    return v;
}
__device__ __forceinline__ float sigm(float x) { return 1.f / (1.f + expf(-x)); }
// round-to-nearest tf32 (kills truncation bias in the tensor unit)
__device__ __forceinline__ float tf32r(float x) {
    uint32_t u;
    asm("cvt.rna.tf32.f32 %0, %1;" : "=r"(u) : "f"(x));
    return __uint_as_float(u);
}

__device__ __forceinline__ void ldsm4(uint32_t& r0, uint32_t& r1,
                                      uint32_t& r2, uint32_t& r3, uint32_t addr) {
    asm volatile("ldmatrix.sync.aligned.m8n8.x4.shared.b16 {%0,%1,%2,%3}, [%4];"
                 : "=r"(r0), "=r"(r1), "=r"(r2), "=r"(r3) : "r"(addr));
}

// ---------------------------------------------------------------------------
// tf32 mma.sync GEMM: C[M,N] = alpha * A[M,K] @ B[N,K]^T   (NT form)
// CTA tile 256x128. Grid: (N/128, M/256, batch). Block: 512 (16 warps, 8x2,
// warp tile 32x64). Single __syncthreads per K-chunk (post-wait barrier
// proves compute(c-1) done before load(c+2) reuses its stage).
// ---------------------------------------------------------------------------
__global__ __launch_bounds__(512, 1)
void gemm_mma_kernel(const float* __restrict__ A, const float* __restrict__ B,
                     float* __restrict__ C, int K,
                     long lda, long ldb, long ldc,
                     long sA, long sB, long sC, float alpha)
{
    extern __shared__ float smem[];
    const uint32_t sb = (uint32_t)__cvta_generic_to_shared(smem);
    A += (long)blockIdx.z * sA;
    B += (long)blockIdx.z * sB;
    C += (long)blockIdx.z * sC;
    const int bm = blockIdx.y * 256, bn = blockIdx.x * 128;
    const int tid = threadIdx.x, wid = tid >> 5, lane = tid & 31;
    const int mw = (wid >> 1) * 32;        // warp m offset (0..224)
    const int nw = (wid & 1) * 64;         // warp n offset (0 or 64)
    const int lr = lane >> 2;              // 0..7
    const int lc = lane & 3;               // 0..3
    const int mI = lane >> 3;              // ldmatrix matrix index 0..3
    const int rowo = lane & 7;

    const int aoff = (mw + (mI & 1) * 8 + rowo) * RS + (mI >> 1) * 4;
    int boff[4];
#pragma unroll
    for (int p = 0; p < 4; p++)
        boff[p] = OP_A + (nw + p * 16 + (mI >> 1) * 8 + rowo) * RS + (mI & 1) * 4;

    // cp.async slots: A 4 float4/thread (2048 total), B 2 float4/thread (1024)
    int arow[4], aq[4], brow[2], bq[2];
#pragma unroll
    for (int t = 0; t < 4; t++) {
        int id = tid + t * 512;
        arow[t] = id >> 3; aq[t] = id & 7;
    }
#pragma unroll
    for (int t = 0; t < 2; t++) {
        int id = tid + t * 512;
        brow[t] = id >> 3; bq[t] = id & 7;
    }
    const int nch = K >> 5;                // K/32 chunks

    auto load_chunk = [&](int c, int s) {
        float* As = smem + s * STAGE_FLOATS;
        float* Bs = As + OP_A;
        long ko = (long)c * 32;
#pragma unroll
        for (int t = 0; t < 4; t++) {
            const float* ga = A + (long)(bm + arow[t]) * lda + ko + aq[t] * 4;
            float* da = As + arow[t] * RS + aq[t] * 4;
            asm volatile("cp.async.cg.shared.global [%0], [%1], 16;"
                         :: "r"((uint32_t)__cvta_generic_to_shared(da)), "l"(ga));
        }
#pragma unroll
        for (int t = 0; t < 2; t++) {
            const float* gb = B + (long)(bn + brow[t]) * ldb + ko + bq[t] * 4;
            float* db = Bs + brow[t] * RS + bq[t] * 4;
            asm volatile("cp.async.cg.shared.global [%0], [%1], 16;"
                         :: "r"((uint32_t)__cvta_generic_to_shared(db)), "l"(gb));
        }
    };

    float acc[2][8][4];
#pragma unroll
    for (int i = 0; i < 2; i++)
#pragma unroll
        for (int j = 0; j < 8; j++)
#pragma unroll
            for (int v = 0; v < 4; v++) acc[i][j][v] = 0.f;

    load_chunk(0, 0);
    asm volatile("cp.async.commit_group;");
    if (nch > 1) {
        load_chunk(1, 1);
        asm volatile("cp.async.commit_group;");
    }

    for (int c = 0; c < nch; c++) {
        if (c + 1 < nch) asm volatile("cp.async.wait_group 1;");
        else             asm volatile("cp.async.wait_group 0;");
        __syncthreads();
        if (c + 2 < nch) {
            load_chunk(c + 2, (c + 2) % 3);     // stage of chunk c-1 (done)
            asm volatile("cp.async.commit_group;");
        }
        const uint32_t stb = sb + (uint32_t)((c % 3) * STAGE_FLOATS) * 4u;
#pragma unroll
        for (int kk = 0; kk < 4; kk++) {
            const uint32_t kb = (uint32_t)(kk * 8) * 4u;
            uint32_t a[2][4];
#pragma unroll
            for (int im = 0; im < 2; im++)
                ldsm4(a[im][0], a[im][1], a[im][2], a[im][3],
                      stb + (uint32_t)(aoff + im * 16 * RS) * 4u + kb);
#pragma unroll
            for (int p = 0; p < 4; p++) {
                uint32_t b0, b1, b2, b3;
                ldsm4(b0, b1, b2, b3, stb + (uint32_t)boff[p] * 4u + kb);
#pragma unroll
                for (int im = 0; im < 2; im++) {
                    asm volatile(
                        "mma.sync.aligned.m16n8k8.row.col.f32.tf32.tf32.f32 "
                        "{%0,%1,%2,%3}, {%4,%5,%6,%7}, {%8,%9}, {%0,%1,%2,%3};"
                        : "+f"(acc[im][2 * p][0]), "+f"(acc[im][2 * p][1]),
                          "+f"(acc[im][2 * p][2]), "+f"(acc[im][2 * p][3])
                        : "r"(a[im][0]), "r"(a[im][1]), "r"(a[im][2]), "r"(a[im][3]),
                          "r"(b0), "r"(b1));
                    asm volatile(
                        "mma.sync.aligned.m16n8k8.row.col.f32.tf32.tf32.f32 "
                        "{%0,%1,%2,%3}, {%4,%5,%6,%7}, {%8,%9}, {%0,%1,%2,%3};"
                        : "+f"(acc[im][2 * p + 1][0]), "+f"(acc[im][2 * p + 1][1]),
                          "+f"(acc[im][2 * p + 1][2]), "+f"(acc[im][2 * p + 1][3])
                        : "r"(a[im][0]), "r"(a[im][1]), "r"(a[im][2]), "r"(a[im][3]),
                          "r"(b2), "r"(b3));
                }
            }
        }
    }

    // epilogue: direct float2 stores
#pragma unroll
    for (int im = 0; im < 2; im++) {
        long r0 = (long)(bm + mw + im * 16 + lr);
#pragma unroll
        for (int jn = 0; jn < 8; jn++) {
            long col = bn + nw + jn * 8 + lc * 2;
            float2 v0 = make_float2(acc[im][jn][0] * alpha, acc[im][jn][1] * alpha);
            float2 v1 = make_float2(acc[im][jn][2] * alpha, acc[im][jn][3] * alpha);
            *reinterpret_cast<float2*>(C + r0 * ldc + col) = v0;
            *reinterpret_cast<float2*>(C + (r0 + 8) * ldc + col) = v1;
        }
    }
}

// ---------------------------------------------------------------------------
// Transpose: in [R,C] -> out [C,R], output rounded to tf32 (RNA).
// ---------------------------------------------------------------------------
__global__ void transpose_kernel(const float* __restrict__ in, float* __restrict__ out,
                                 int R, int C, long sIn, long sOut)
{
    __shared__ float t[32][33];
    in  += (long)blockIdx.z * sIn;
    out += (long)blockIdx.z * sOut;
    int bx = blockIdx.x * 32, by = blockIdx.y * 32;
    int x = threadIdx.x, y = threadIdx.y;
#pragma unroll
    for (int i = 0; i < 32; i += 8) t[y + i][x] = in[(long)(by + y + i) * C + bx + x];
    __syncthreads();
#pragma unroll
    for (int i = 0; i < 32; i += 8)
        out[(long)(bx + y + i) * R + by + x] = tf32r(t[x][y + i]);
}

// 4 x [512,512] weight transposes in one launch (z selects the weight)
__global__ void transpose4_kernel(const float* __restrict__ w0, const float* __restrict__ w1,
                                  const float* __restrict__ w2, const float* __restrict__ w3,
                                  float* __restrict__ o0, float* __restrict__ o1,
                                  float* __restrict__ o2, float* __restrict__ o3)
{
    __shared__ float t[32][33];
    const float* in; float* out;
    switch (blockIdx.z) {
        case 0: in = w0; out = o0; break;
        case 1: in = w1; out = o1; break;
        case 2: in = w2; out = o2; break;
        default: in = w3; out = o3; break;
    }
    int bx = blockIdx.x * 32, by = blockIdx.y * 32;
    int x = threadIdx.x, y = threadIdx.y;
#pragma unroll
    for (int i = 0; i < 32; i += 8) t[y + i][x] = in[(long)(by + y + i) * kD + bx + x];
    __syncthreads();
#pragma unroll
    for (int i = 0; i < 32; i += 8)
        out[(long)(bx + y + i) * kD + by + x] = tf32r(t[x][y + i]);
}

// ---------------------------------------------------------------------------
// LN over 3D=1536, split + sigmoid into Z / HG / PL. block=384, grid=TB.
// ---------------------------------------------------------------------------
__global__ void ln_preact_kernel(const float* __restrict__ pre,
                                 const float* __restrict__ g, const float* __restrict__ bb,
                                 float* __restrict__ Z, float* __restrict__ HG,
                                 float* __restrict__ PL)
{
    __shared__ float sh[32];
    long row = blockIdx.x;
    int c = threadIdx.x * 4;
    const float* r = pre + row * (3 * kD);
    float4 v = *reinterpret_cast<const float4*>(r + c);
    float s = v.x + v.y + v.z + v.w;
    float q = v.x * v.x + v.y * v.y + v.z * v.z + v.w * v.w;
    s = blockSum(s, sh);
    q = blockSum(q, sh);
    const float invW = 1.f / (3 * kD);
    float m  = s * invW;
    float rv = rsqrtf(q * invW - m * m + kEPS);
    float n0 = g[c + 0] * ((v.x - m) * rv) + bb[c + 0];
    float n1 = g[c + 1] * ((v.y - m) * rv) + bb[c + 1];
    float n2 = g[c + 2] * ((v.z - m) * rv) + bb[c + 2];
    float n3 = g[c + 3] * ((v.w - m) * rv) + bb[c + 3];
    long rD = row * kD;
    if (c < kD) {
        float4 o = make_float4(sigm(n0), sigm(n1), sigm(n2), sigm(n3));
        *reinterpret_cast<float4*>(Z + rD + c) = o;
    } else if (c < 2 * kD) {
        float4 o = make_float4(sigm(n0), sigm(n1), sigm(n2), sigm(n3));
        *reinterpret_cast<float4*>(HG + rD + (c - kD)) = o;
    } else {
        float4 o = make_float4(n0, n1, n2, n3);
        *reinterpret_cast<float4*>(PL + rD + (c - 2 * kD)) = o;
    }
}

// In-place LN over D=512, output rounded to tf32. block=128, grid=rows.
__global__ void ln512_kernel(float* __restrict__ x,
                             const float* __restrict__ g, const float* __restrict__ b)
{
    __shared__ float sh[32];
    long row = blockIdx.x;
    int c = threadIdx.x * 4;
    float* r = x + row * kD;
    float4 v = *reinterpret_cast<const float4*>(r + c);
    float s = v.x + v.y + v.z + v.w;
    float q = v.x * v.x + v.y * v.y + v.z * v.z + v.w * v.w;
    s = blockSum(s, sh);
    q = blockSum(q, sh);
    const float invW = 1.f / kD;
    float m  = s * invW;
    float rv = rsqrtf(q * invW - m * m + kEPS);
    v.x = tf32r(g[c + 0] * ((v.x - m) * rv) + b[c + 0]);
    v.y = tf32r(g[c + 1] * ((v.y - m) * rv) + b[c + 1]);
    v.z = tf32r(g[c + 2] * ((v.z - m) * rv) + b[c + 2]);
    v.w = tf32r(g[c + 3] * ((v.w - m) * rv) + b[c + 3]);
    *reinterpret_cast<float4*>(r + c) = v;
}

// SRU linear recurrence with batched prefetch (MLP 32/thread).
__global__ __launch_bounds__(128)
void scan_kernel(const float* __restrict__ Z, const float* __restrict__ PL,
                 const float* __restrict__ h0, float* __restrict__ ss)
{
    constexpr int BATCH = 16;
    int idx = blockIdx.x * 128 + threadIdx.x;          // b*D + d
    float s = h0[idx];
    const long stride = (long)kB * kD;
    long off = idx;
    for (int g = 0; g < kT / BATCH; g++) {
        float z[BATCH], p[BATCH];
#pragma unroll
        for (int j = 0; j < BATCH; j++) z[j] = __ldg(Z + off + j * stride);
#pragma unroll
        for (int j = 0; j < BATCH; j++) p[j] = __ldg(PL + off + j * stride);
#pragma unroll
        for (int j = 0; j < BATCH; j++) {
            s = (1.f - z[j]) * s + z[j] * p[j];
            ss[off + j * stride] = s;
        }
        off += (long)BATCH * stride;
    }
}

// Masked softmax over S=512; rounded probs into av, exact probs into p_attn.
__global__ void softmax_kernel(float* __restrict__ av, float* __restrict__ pattn,
                               const int* __restrict__ mlen)
{
    __shared__ float sh[32];
    long row = blockIdx.x;                 // b*T + t
    int b = (int)(row / kT), t = (int)(row % kT);
    int ml = mlen[b];
    float* r = av + row * kS;
    int c = threadIdx.x * 4;
    float4 v = *reinterpret_cast<const float4*>(r + c);
    const float inv = rsqrtf((float)kD);
    float x0 = v.x * inv, x1 = v.y * inv, x2 = v.z * inv, x3 = v.w * inv;
    float mx = -INFINITY;
    if (c + 0 < ml) mx = fmaxf(mx, x0);
    if (c + 1 < ml) mx = fmaxf(mx, x1);
    if (c + 2 < ml) mx = fmaxf(mx, x2);
    if (c + 3 < ml) mx = fmaxf(mx, x3);
    mx = blockMax(mx, sh);
    float e0 = (c + 0 < ml) ? expf(x0 - mx) : 0.f;
    float e1 = (c + 1 < ml) ? expf(x1 - mx) : 0.f;
    float e2 = (c + 2 < ml) ? expf(x2 - mx) : 0.f;
    float e3 = (c + 3 < ml) ? expf(x3 - mx) : 0.f;
    float sum = blockSum(e0 + e1 + e2 + e3, sh);
    float is = 1.f / sum;
    float4 o = make_float4(e0 * is, e1 * is, e2 * is, e3 * is);
    *reinterpret_cast<float4*>(pattn + ((long)t * kB + b) * kS + c) = o;
    float4 oq = make_float4(tf32r(o.x), tf32r(o.y), tf32r(o.z), tf32r(o.w));
    *reinterpret_cast<float4*>(r + c) = oq;
}

// out = (1-hg)*tanh(LN(h1)+LN(h2)) + hg*prev
__global__ void final_kernel(const float* __restrict__ h1, const float* __restrict__ h2,
                             const float* __restrict__ HG, const float* __restrict__ prev,
                             const float* __restrict__ g_h, const float* __restrict__ b_h,
                             const float* __restrict__ g_c, const float* __restrict__ b_c,
                             float* __restrict__ out)
{
    __shared__ float sh[32];
    long row = blockIdx.x;
    int c = threadIdx.x * 4;
    float4 a = *reinterpret_cast<const float4*>(h1 + row * kD + c);
    float4 d = *reinterpret_cast<const float4*>(h2 + row * kD + c);
    float s1 = a.x + a.y + a.z + a.w;
    float q1 = a.x * a.x + a.y * a.y + a.z * a.z + a.w * a.w;
    float s2 = d.x + d.y + d.z + d.w;
    float q2 = d.x * d.x + d.y * d.y + d.z * d.z + d.w * d.w;
    s1 = blockSum(s1, sh);
    q1 = blockSum(q1, sh);
    s2 = blockSum(s2, sh);
    q2 = blockSum(q2, sh);
    const float invW = 1.f / kD;
    float m1 = s1 * invW, r1 = rsqrtf(q1 * invW - m1 * m1 + kEPS);
    float m2 = s2 * invW, r2 = rsqrtf(q2 * invW - m2 * m2 + kEPS);
    float4 hg = *reinterpret_cast<const float4*>(HG + row * kD + c);
    float4 pv = *reinterpret_cast<const float4*>(prev + row * kD + c);
    float t0 = tanhf(g_h[c + 0] * ((a.x - m1) * r1) + b_h[c + 0] +
                     g_c[c + 0] * ((d.x - m2) * r2) + b_c[c + 0]);
    float t1 = tanhf(g_h[c + 1] * ((a.y - m1) * r1) + b_h[c + 1] +
                     g_c[c + 1] * ((d.y - m2) * r2) + b_c[c + 1]);
    float t2 = tanhf(g_h[c + 2] * ((a.z - m1) * r1) + b_h[c + 2] +
                     g_c[c + 2] * ((d.z - m2) * r2) + b_c[c + 2]);
    float t3 = tanhf(g_h[c + 3] * ((a.w - m1) * r1) + b_h[c + 3] +
                     g_c[c + 3] * ((d.w - m2) * r2) + b_c[c + 3]);
    float4 o;
    o.x = (1.f - hg.x) * t0 + hg.x * pv.x;
    o.y = (1.f - hg.y) * t1 + hg.y * pv.y;
    o.z = (1.f - hg.z) * t2 + hg.z * pv.z;
    o.w = (1.f - hg.w) * t3 + hg.w * pv.w;
    *reinterpret_cast<float4*>(out + row * kD + c) = o;
}

// ---------------------------------------------------------------------------
// Launch
// ---------------------------------------------------------------------------
extern "C" void kernel_launch(void* const* d_in, const int* in_sizes, int n_in,
                              void* d_out, int out_size)
{
    int i_prev = -1, i_enc = -1, i_hidden = -1, i_ml = -1, i_Win = -1;
    int w4[4] = {-1, -1, -1, -1}; int n4 = 0;
    int p2[2] = {-1, -1};         int np = 0;
    int v8[8] = {-1, -1, -1, -1, -1, -1, -1, -1}; int nv = 0;
    for (int i = 0; i < n_in; i++) {
        switch (in_sizes[i]) {
            case 8388608: if (i_prev < 0) i_prev = i; else i_enc = i; break;
            case 16384:   i_hidden = i; break;
            case 32:      i_ml = i; break;
            case 786432:  i_Win = i; break;
            case 262144:  if (n4 < 4) w4[n4++] = i; break;
            case 1536:    if (np < 2) p2[np++] = i; break;
            case 512:     if (nv < 8) v8[nv++] = i; break;
            default: break;
        }
    }
    const float* prev   = (const float*)d_in[i_prev];
    const float* hidden = (const float*)d_in[i_hidden];
    const float* enc    = (const float*)d_in[i_enc];
    const int*   mlen   = (const int*)d_in[i_ml];
    const float* W_in   = (const float*)d_in[i_Win];
    const float* W_enc  = (const float*)d_in[w4[0]];
    const float* W_att  = (const float*)d_in[w4[1]];
    const float* W_hid  = (const float*)d_in[w4[2]];
    const float* W_ctx  = (const float*)d_in[w4[3]];
    const float* g_pre  = (const float*)d_in[p2[0]];
    const float* b_pre  = (const float*)d_in[p2[1]];
    const float* g_enc  = (const float*)d_in[v8[0]];
    const float* b_enc  = (const float*)d_in[v8[1]];
    const float* g_att  = (const float*)d_in[v8[2]];
    const float* b_att  = (const float*)d_in[v8[3]];
    const float* g_h    = (const float*)d_in[v8[4]];
    const float* b_h    = (const float*)d_in[v8[5]];
    const float* g_c    = (const float*)d_in[v8[6]];
    const float* b_c    = (const float*)d_in[v8[7]];

    float* sc = nullptr;
    cudaGetSymbolAddress((void**)&sc, g_scratch);

    float* out       = (float*)d_out;            // [T,B,D]
    float* out_hid   = out + kTBD;               // [B,D]
    float* out_pattn = out_hid + (long)kB * kD;  // [T,B,S]

    cudaFuncSetAttribute(gemm_mma_kernel,
                         cudaFuncAttributeMaxDynamicSharedMemorySize, GEMM_SMEM);

    dim3 tb(32, 8);
    const float invsq = rsqrtf((float)kD);

    // side stream + fork/join events (capture-safe; not destroyed mid-capture)
    cudaStream_t s1;
    cudaStreamCreateWithFlags(&s1, cudaStreamNonBlocking);
    cudaEvent_t eW, eP, eS, eH;
    cudaEventCreateWithFlags(&eW, cudaEventDisableTiming);
    cudaEventCreateWithFlags(&eP, cudaEventDisableTiming);
    cudaEventCreateWithFlags(&eS, cudaEventDisableTiming);
    cudaEventCreateWithFlags(&eH, cudaEventDisableTiming);

    // 0) weight transposes on stream 0 (-> K-major [N,K], rounded tf32)
    transpose_kernel<<<dim3(16, 16, 3), tb>>>(W_in, sc + OF_WTIN, kD, 3 * kD,
                                              512, (long)kD * kD);
    transpose4_kernel<<<dim3(16, 16, 4), tb>>>(W_enc, W_att, W_hid, W_ctx,
                                               sc + OF_WTENC, sc + OF_WTATT,
                                               sc + OF_WTHID, sc + OF_WTCTX);
    cudaEventRecord(eW, 0);

    // -- side stream: enc chain (pctx) --
    cudaStreamWaitEvent(s1, eW, 0);
    gemm_mma_kernel<<<dim3(4, 64, 1), 512, GEMM_SMEM, s1>>>(
        enc, sc + OF_WTENC, sc + OF_PCTX, 512, 512, 512, 512, 0, 0, 0, 1.f);
    ln512_kernel<<<(unsigned)kTB, 128, 0, s1>>>(sc + OF_PCTX, g_enc, b_enc);
    transpose_kernel<<<dim3(16, 16, 32), tb, 0, s1>>>(sc + OF_PCTX, sc + OF_PCTXT,
                                                      kS, kD, (long)kS * kD,
                                                      (long)kD * kS);
    cudaEventRecord(eP, s1);

    // -- main stream: preact chain --
    gemm_mma_kernel<<<dim3(12, 64, 1), 512, GEMM_SMEM>>>(
        prev, sc + OF_WTIN, sc + OF_PRE, 512, 512, 512, 1536, 0, 0, 0, 1.f);
    ln_preact_kernel<<<(unsigned)kTB, 384>>>(sc + OF_PRE, g_pre, b_pre,
                                             sc + OF_Z, sc + OF_HG, sc + OF_PL);
    scan_kernel<<<(kB * kD) / 128, 128>>>(sc + OF_Z, sc + OF_PL, hidden, sc + OF_SS);
    cudaEventRecord(eS, 0);
    gemm_mma_kernel<<<dim3(4, 64, 1), 512, GEMM_SMEM>>>(
        sc + OF_SS, sc + OF_WTATT, sc + OF_ATT, 512, 512, 512, 512, 0, 0, 0, 1.f);
    ln512_kernel<<<(unsigned)kTB, 128>>>(sc + OF_ATT, g_att, b_att);

    // -- side stream: h1 = ss @ W_hidden (after scan) --
    cudaStreamWaitEvent(s1, eS, 0);
    gemm_mma_kernel<<<dim3(4, 64, 1), 512, GEMM_SMEM, s1>>>(
        sc + OF_SS, sc + OF_WTHID, sc + OF_H1, 512, 512, 512, 512, 0, 0, 0, 1.f);
    cudaEventRecord(eH, s1);

    // -- main stream: attention (needs pctx) --
    cudaStreamWaitEvent(0, eP, 0);
    gemm_mma_kernel<<<dim3(4, 2, 32), 512, GEMM_SMEM>>>(
        sc + OF_ATT, sc + OF_PCTX, sc + OF_AV, 512,
        (long)kB * kD, 512, 512, kD, (long)kS * kD, (long)kT * kS, 1.f);
    softmax_kernel<<<(unsigned)(kB * kT), 128>>>(sc + OF_AV, out_pattn, mlen);
    gemm_mma_kernel<<<dim3(4, 2, 32), 512, GEMM_SMEM>>>(
        sc + OF_AV, sc + OF_PCTXT, sc + OF_AO, 512,
        512, 512, (long)kB * kD, (long)kT * kS, (long)kD * kS, kD, invsq);
    gemm_mma_kernel<<<dim3(4, 64, 1), 512, GEMM_SMEM>>>(
        sc + OF_AO, sc + OF_WTCTX, sc + OF_H2, 512, 512, 512, 512, 0, 0, 0, 1.f);

    // join h1, final blend
    cudaStreamWaitEvent(0, eH, 0);
    final_kernel<<<(unsigned)kTB, 128>>>(sc + OF_H1, sc + OF_H2, sc + OF_HG, prev,
                                         g_h, b_h, g_c, b_c, out);
    cudaMemcpyAsync(out_hid, sc + OF_SS + (long)(kT - 1) * kB * kD,
                    (size_t)kB * kD * sizeof(float), cudaMemcpyDeviceToDevice, 0);
    // (stream/events intentionally leaked: destroying a fork stream mid-capture
    //  invalidates the capture)
}

// round 10
// speedup vs baseline: 2.1239x; 2.1239x over previous
#include <cuda_runtime.h>
#include <cuda_fp16.h>
#include <math.h>
#include <stdint.h>

// ---------------------------------------------------------------------------
// AttSRU: T=512, B=32, S=512, D=512, fp32.
// Round 10: fp16 m16n8k16 mma GEMMs (2x tf32 rate, half operand traffic),
// fp32 accumulate. 128x128 CTA tiles, 2 CTAs/SM, 3-stage cp.async.
// ---------------------------------------------------------------------------

namespace {
constexpr int  kT = 512, kB = 32, kS = 512, kD = 512;
constexpr long kTB   = (long)kT * kB;      // 16384 rows
constexpr long kTBD  = kTB * kD;           // 8388608
constexpr long kPRE  = kTB * 3 * kD;       // 25165824
constexpr float kEPS = 1e-6f;

// fp32 scratch offsets
constexpr long OF_PRE    = 0;                  // [TB,3D]
constexpr long OF_Z      = kPRE;               // [T,B,D]
constexpr long OF_HG     = OF_Z    + kTBD;
constexpr long OF_PL     = OF_HG   + kTBD;
constexpr long OF_PCTX32 = OF_PL   + kTBD;     // enc GEMM out (pre-LN)
constexpr long OF_ATT32  = OF_PCTX32 + kTBD;   // attn GEMM out (pre-LN)
constexpr long OF_AV32   = OF_ATT32  + kTBD;   // align scores
constexpr long OF_H1     = OF_AV32   + kTBD;
constexpr long OF_H2     = OF_H1     + kTBD;
constexpr long OF_SSL    = OF_H2     + kTBD;   // [B,D] final scan state
constexpr long kSCF      = OF_SSL + (long)kB * kD;

// fp16 scratch offsets
constexpr long HF_PREV  = 0;                   // [T,B,D]
constexpr long HF_ENC   = HF_PREV  + kTBD;     // [B,S,D]
constexpr long HF_PCTX  = HF_ENC   + kTBD;     // LN(enc@W_enc)
constexpr long HF_PCTXT = HF_PCTX  + kTBD;     // [B,D,S]
constexpr long HF_SS    = HF_PCTXT + kTBD;     // scan states
constexpr long HF_ATT   = HF_SS    + kTBD;     // LN(ss@W_attn)
constexpr long HF_AV    = HF_ATT   + kTBD;     // softmax probs
constexpr long HF_AO    = HF_AV    + kTBD;     // attn_out
constexpr long HF_WTIN  = HF_AO    + kTBD;     // [3D,D]
constexpr long HF_WTENC = HF_WTIN  + (long)3 * kD * kD;
constexpr long HF_WTATT = HF_WTENC + (long)kD * kD;
constexpr long HF_WTHID = HF_WTATT + (long)kD * kD;
constexpr long HF_WTCTX = HF_WTHID + (long)kD * kD;
constexpr long kSCH     = HF_WTCTX + (long)kD * kD;

// fp16 GEMM smem: K-chunk 32 halfs/row, row stride 40 halfs (80B; conflict-free)
constexpr int RSH = 40;                       // halfs per smem row
constexpr int OPH = 128 * RSH;                // halfs per operand per stage
constexpr int STG = 2 * OPH;                  // halfs per stage (A+B)
constexpr int GEMM_SMEM = 3 * STG * 2;        // 61440 B -> 2 CTAs/SM
}

__device__ float  g_scf[kSCF];
__device__ __half g_sch[kSCH];

// ---------------------------------------------------------------------------
// Helpers
// ---------------------------------------------------------------------------
__device__ __forceinline__ float warpSum(float v) {
#pragma unroll
    for (int o = 16; o; o >>= 1) v += __shfl_xor_sync(0xffffffffu, v, o);
    return v;
}
__device__ __forceinline__ float warpMax(float v) {
#pragma unroll
    for (int o = 16; o; o >>= 1) v = fmaxf(v, __shfl_xor_sync(0xffffffffu, v, o));
    return v;
}
__device__ __forceinline__ float blockSum(float v, float* sh) {
    int w = threadIdx.x >> 5, l = threadIdx.x & 31, nw = blockDim.x >> 5;
    v = warpSum(v);
    if (l == 0) sh[w] = v;
    __syncthreads();
    v = (l < nw) ? sh[l] : 0.f;
    v = warpSum(v);
    __syncthreads();
    return v;
}
__device__ __forceinline__ float blockMax(float v, float* sh) {
    int w = threadIdx.x >> 5, l = threadIdx.x & 31, nw = blockDim.x >> 5;
    v = warpMax(v);
    if (l == 0) sh[w] = v;
    __syncthreads();
    v = (l < nw) ? sh[l] : -INFINITY;
    v = warpMax(v);
    __syncthreads();
    return v;
}
__device__ __forceinline__ float sigm(float x) { return 1.f / (1.f + expf(-x)); }

__device__ __forceinline__ void ldsm4(uint32_t& r0, uint32_t& r1,
                                      uint32_t& r2, uint32_t& r3, uint32_t addr) {
    asm volatile("ldmatrix.sync.aligned.m8n8.x4.shared.b16 {%0,%1,%2,%3}, [%4];"
                 : "=r"(r0), "=r"(r1), "=r"(r2), "=r"(r3) : "r"(addr));
}

__device__ __forceinline__ void storeC(float* C, long off, float x, float y) {
    *reinterpret_cast<float2*>(C + off) = make_float2(x, y);
}
__device__ __forceinline__ void storeC(__half* C, long off, float x, float y) {
    *reinterpret_cast<__half2*>(C + off) = __floats2half2_rn(x, y);
}

// ---------------------------------------------------------------------------
// fp16 mma GEMM: C[M,N] = alpha * A[M,K] @ B[N,K]^T   (NT form, fp32 accum)
// A, B __half K-major (lda/ldb element strides). M%128==0, N%128==0, K%32==0.
// Grid: (N/128, M/128, batch). Block: 256 (8 warps 4x2, warp tile 32x64).
// ---------------------------------------------------------------------------
template <typename OutT>
__global__ __launch_bounds__(256, 2)
void gemm_h_kernel(const __half* __restrict__ A, const __half* __restrict__ B,
                   OutT* __restrict__ C, int K,
                   long lda, long ldb, long ldc,
                   long sA, long sB, long sC, float alpha)
{
    extern __shared__ __half smh[];
    const uint32_t sb = (uint32_t)__cvta_generic_to_shared(smh);
    A += (long)blockIdx.z * sA;
    B += (long)blockIdx.z * sB;
    C += (long)blockIdx.z * sC;
    const int bm = blockIdx.y * 128, bn = blockIdx.x * 128;
    const int tid = threadIdx.x, wid = tid >> 5, lane = tid & 31;
    const int mw = (wid >> 1) * 32, nw = (wid & 1) * 64;
    const int lr = lane >> 2, lc = lane & 3;

    // ldmatrix per-lane offsets (halfs within a stage)
    // A m16 tile: lane l -> row (l&15), k-offset (l>>4)*8
    const int aoff = (mw + (lane & 15)) * RSH + (lane >> 4) * 8;
    // B pair p (two n8 tiles): lane l -> n row (l&7)+(l>>4)*8, k-off ((l>>3)&1)*8
    const int boff0 = OPH + (nw + (lane & 7) + (lane >> 4) * 8) * RSH
                    + ((lane >> 3) & 1) * 8;

    // cp.async slots: 4 x 16B per thread (i<2 -> A rows, else B rows)
    const __half* gp[4];
    uint32_t dsto[4];
#pragma unroll
    for (int i = 0; i < 4; i++) {
        int id = tid + i * 256;          // 0..1023
        bool isA = id < 512;
        int rid = id & 511;
        int row = rid >> 2, q = rid & 3;
        gp[i] = (isA ? A + (long)(bm + row) * lda
                     : B + (long)(bn + row) * ldb) + q * 8;
        dsto[i] = (isA ? 0u : (uint32_t)OPH) + (uint32_t)(row * RSH + q * 8);
    }
    const int nch = K >> 5;              // K/32 chunks

    auto load_chunk = [&](int c, int s) {
        long ko = (long)c * 32;
        uint32_t base = (uint32_t)(s * STG);
#pragma unroll
        for (int i = 0; i < 4; i++) {
            uint32_t d = sb + (base + dsto[i]) * 2u;
            asm volatile("cp.async.cg.shared.global [%0], [%1], 16;"
                         :: "r"(d), "l"(gp[i] + ko));
        }
    };

    float acc[2][8][4];
#pragma unroll
    for (int i = 0; i < 2; i++)
#pragma unroll
        for (int j = 0; j < 8; j++)
#pragma unroll
            for (int v = 0; v < 4; v++) acc[i][j][v] = 0.f;

    load_chunk(0, 0);
    asm volatile("cp.async.commit_group;");
    if (nch > 1) {
        load_chunk(1, 1);
        asm volatile("cp.async.commit_group;");
    }

    for (int c = 0; c < nch; c++) {
        if (c + 1 < nch) asm volatile("cp.async.wait_group 1;");
        else             asm volatile("cp.async.wait_group 0;");
        __syncthreads();
        if (c + 2 < nch) {
            load_chunk(c + 2, (c + 2) % 3);     // stage of chunk c-1 (done)
            asm volatile("cp.async.commit_group;");
        }
        const uint32_t stb = sb + (uint32_t)((c % 3) * STG) * 2u;
#pragma unroll
        for (int ks = 0; ks < 2; ks++) {        // two k16 steps per chunk
            const uint32_t kb = (uint32_t)(ks * 16) * 2u;
            uint32_t a[2][4];
#pragma unroll
            for (int im = 0; im < 2; im++)
                ldsm4(a[im][0], a[im][1], a[im][2], a[im][3],
                      stb + (uint32_t)(aoff + im * 16 * RSH) * 2u + kb);
#pragma unroll
            for (int p = 0; p < 4; p++) {
                uint32_t b0, b1, b2, b3;
                ldsm4(b0, b1, b2, b3, stb + (uint32_t)(boff0 + p * 16 * RSH) * 2u + kb);
#pragma unroll
                for (int im = 0; im < 2; im++) {
                    asm volatile(
                        "mma.sync.aligned.m16n8k16.row.col.f32.f16.f16.f32 "
                        "{%0,%1,%2,%3}, {%4,%5,%6,%7}, {%8,%9}, {%0,%1,%2,%3};"
                        : "+f"(acc[im][2 * p][0]), "+f"(acc[im][2 * p][1]),
                          "+f"(acc[im][2 * p][2]), "+f"(acc[im][2 * p][3])
                        : "r"(a[im][0]), "r"(a[im][1]), "r"(a[im][2]), "r"(a[im][3]),
                          "r"(b0), "r"(b1));
                    asm volatile(
                        "mma.sync.aligned.m16n8k16.row.col.f32.f16.f16.f32 "
                        "{%0,%1,%2,%3}, {%4,%5,%6,%7}, {%8,%9}, {%0,%1,%2,%3};"
                        : "+f"(acc[im][2 * p + 1][0]), "+f"(acc[im][2 * p + 1][1]),
                          "+f"(acc[im][2 * p + 1][2]), "+f"(acc[im][2 * p + 1][3])
                        : "r"(a[im][0]), "r"(a[im][1]), "r"(a[im][2]), "r"(a[im][3]),
                          "r"(b2), "r"(b3));
                }
            }
        }
    }

    // epilogue
#pragma unroll
    for (int im = 0; im < 2; im++) {
        long r0 = (long)(bm + mw + im * 16 + lr);
#pragma unroll
        for (int jn = 0; jn < 8; jn++) {
            long col = bn + nw + jn * 8 + lc * 2;
            storeC(C, r0 * ldc + col, acc[im][jn][0] * alpha, acc[im][jn][1] * alpha);
            storeC(C, (r0 + 8) * ldc + col, acc[im][jn][2] * alpha, acc[im][jn][3] * alpha);
        }
    }
}

// ---------------------------------------------------------------------------
// fp32 -> fp16 convert (vectorized)
// ---------------------------------------------------------------------------
__global__ void f2h_kernel(const float* __restrict__ in, __half* __restrict__ out,
                           long n4)
{
    long i = (long)blockIdx.x * blockDim.x + threadIdx.x;
    if (i >= n4) return;
    float4 v = reinterpret_cast<const float4*>(in)[i];
    __half2 h0 = __floats2half2_rn(v.x, v.y);
    __half2 h1 = __floats2half2_rn(v.z, v.w);
    reinterpret_cast<__half2*>(out)[i * 2]     = h0;
    reinterpret_cast<__half2*>(out)[i * 2 + 1] = h1;
}

// ---------------------------------------------------------------------------
// Transposes
// ---------------------------------------------------------------------------
__global__ void transpose_f2h_kernel(const float* __restrict__ in,
                                     __half* __restrict__ out,
                                     int R, int C, long sIn, long sOut)
{
    __shared__ float t[32][33];
    in  += (long)blockIdx.z * sIn;
    out += (long)blockIdx.z * sOut;
    int bx = blockIdx.x * 32, by = blockIdx.y * 32;
    int x = threadIdx.x, y = threadIdx.y;
#pragma unroll
    for (int i = 0; i < 32; i += 8) t[y + i][x] = in[(long)(by + y + i) * C + bx + x];
    __syncthreads();
#pragma unroll
    for (int i = 0; i < 32; i += 8)
        out[(long)(bx + y + i) * R + by + x] = __float2half_rn(t[x][y + i]);
}

__global__ void transpose4_f2h_kernel(const float* __restrict__ w0, const float* __restrict__ w1,
                                      const float* __restrict__ w2, const float* __restrict__ w3,
                                      __half* __restrict__ o0, __half* __restrict__ o1,
                                      __half* __restrict__ o2, __half* __restrict__ o3)
{
    __shared__ float t[32][33];
    const float* in; __half* out;
    switch (blockIdx.z) {
        case 0: in = w0; out = o0; break;
        case 1: in = w1; out = o1; break;
        case 2: in = w2; out = o2; break;
        default: in = w3; out = o3; break;
    }
    int bx = blockIdx.x * 32, by = blockIdx.y * 32;
    int x = threadIdx.x, y = threadIdx.y;
#pragma unroll
    for (int i = 0; i < 32; i += 8) t[y + i][x] = in[(long)(by + y + i) * kD + bx + x];
    __syncthreads();
#pragma unroll
    for (int i = 0; i < 32; i += 8)
        out[(long)(bx + y + i) * kD + by + x] = __float2half_rn(t[x][y + i]);
}

__global__ void transpose_h2h_kernel(const __half* __restrict__ in,
                                     __half* __restrict__ out,
                                     int R, int C, long sIn, long sOut)
{
    __shared__ __half t[32][34];
    in  += (long)blockIdx.z * sIn;
    out += (long)blockIdx.z * sOut;
    int bx = blockIdx.x * 32, by = blockIdx.y * 32;
    int x = threadIdx.x, y = threadIdx.y;
#pragma unroll
    for (int i = 0; i < 32; i += 8) t[y + i][x] = in[(long)(by + y + i) * C + bx + x];
    __syncthreads();
#pragma unroll
    for (int i = 0; i < 32; i += 8)
        out[(long)(bx + y + i) * R + by + x] = t[x][y + i];
}

// ---------------------------------------------------------------------------
// LN over 3D=1536, split + sigmoid into Z / HG / PL (fp32). block=384.
// ---------------------------------------------------------------------------
__global__ void ln_preact_kernel(const float* __restrict__ pre,
                                 const float* __restrict__ g, const float* __restrict__ bb,
                                 float* __restrict__ Z, float* __restrict__ HG,
                                 float* __restrict__ PL)
{
    __shared__ float sh[32];
    long row = blockIdx.x;
    int c = threadIdx.x * 4;
    const float* r = pre + row * (3 * kD);
    float4 v = *reinterpret_cast<const float4*>(r + c);
    float s = v.x + v.y + v.z + v.w;
    float q = v.x * v.x + v.y * v.y + v.z * v.z + v.w * v.w;
    s = blockSum(s, sh);
    q = blockSum(q, sh);
    const float invW = 1.f / (3 * kD);
    float m  = s * invW;
    float rv = rsqrtf(q * invW - m * m + kEPS);
    float n0 = g[c + 0] * ((v.x - m) * rv) + bb[c + 0];
    float n1 = g[c + 1] * ((v.y - m) * rv) + bb[c + 1];
    float n2 = g[c + 2] * ((v.z - m) * rv) + bb[c + 2];
    float n3 = g[c + 3] * ((v.w - m) * rv) + bb[c + 3];
    long rD = row * kD;
    if (c < kD) {
        float4 o = make_float4(sigm(n0), sigm(n1), sigm(n2), sigm(n3));
        *reinterpret_cast<float4*>(Z + rD + c) = o;
    } else if (c < 2 * kD) {
        float4 o = make_float4(sigm(n0), sigm(n1), sigm(n2), sigm(n3));
        *reinterpret_cast<float4*>(HG + rD + (c - kD)) = o;
    } else {
        float4 o = make_float4(n0, n1, n2, n3);
        *reinterpret_cast<float4*>(PL + rD + (c - 2 * kD)) = o;
    }
}

// LN over D=512: fp32 in -> fp16 out. block=128, grid=rows.
__global__ void ln512h_kernel(const float* __restrict__ x, __half* __restrict__ out,
                              const float* __restrict__ g, const float* __restrict__ b)
{
    __shared__ float sh[32];
    long row = blockIdx.x;
    int c = threadIdx.x * 4;
    float4 v = *reinterpret_cast<const float4*>(x + row * kD + c);
    float s = v.x + v.y + v.z + v.w;
    float q = v.x * v.x + v.y * v.y + v.z * v.z + v.w * v.w;
    s = blockSum(s, sh);
    q = blockSum(q, sh);
    const float invW = 1.f / kD;
    float m  = s * invW;
    float rv = rsqrtf(q * invW - m * m + kEPS);
    float n0 = g[c + 0] * ((v.x - m) * rv) + b[c + 0];
    float n1 = g[c + 1] * ((v.y - m) * rv) + b[c + 1];
    float n2 = g[c + 2] * ((v.z - m) * rv) + b[c + 2];
    float n3 = g[c + 3] * ((v.w - m) * rv) + b[c + 3];
    __half2* o = reinterpret_cast<__half2*>(out + row * kD + c);
    o[0] = __floats2half2_rn(n0, n1);
    o[1] = __floats2half2_rn(n2, n3);
}

// SRU scan: fp32 state, fp16 ss output, fp32 final state row.
__global__ __launch_bounds__(128)
void scan_kernel(const float* __restrict__ Z, const float* __restrict__ PL,
                 const float* __restrict__ h0, __half* __restrict__ ssh,
                 float* __restrict__ sslast)
{
    constexpr int BATCH = 16;
    int idx = blockIdx.x * 128 + threadIdx.x;          // b*D + d
    float s = h0[idx];
    const long stride = (long)kB * kD;
    long off = idx;
    for (int g = 0; g < kT / BATCH; g++) {
        float z[BATCH], p[BATCH];
#pragma unroll
        for (int j = 0; j < BATCH; j++) z[j] = __ldg(Z + off + j * stride);
#pragma unroll
        for (int j = 0; j < BATCH; j++) p[j] = __ldg(PL + off + j * stride);
#pragma unroll
        for (int j = 0; j < BATCH; j++) {
            s = (1.f - z[j]) * s + z[j] * p[j];
            ssh[off + j * stride] = __float2half_rn(s);
        }
        off += (long)BATCH * stride;
    }
    sslast[idx] = s;
}

// Masked softmax over S=512: fp32 scores in; exact fp32 p_attn out + fp16 probs.
__global__ void softmax_kernel(const float* __restrict__ av32, __half* __restrict__ avh,
                               float* __restrict__ pattn, const int* __restrict__ mlen)
{
    __shared__ float sh[32];
    long row = blockIdx.x;                 // b*T + t
    int b = (int)(row / kT), t = (int)(row % kT);
    int ml = mlen[b];
    const float* r = av32 + row * kS;
    int c = threadIdx.x * 4;
    float4 v = *reinterpret_cast<const float4*>(r + c);
    const float inv = rsqrtf((float)kD);
    float x0 = v.x * inv, x1 = v.y * inv, x2 = v.z * inv, x3 = v.w * inv;
    float mx = -INFINITY;
    if (c + 0 < ml) mx = fmaxf(mx, x0);
    if (c + 1 < ml) mx = fmaxf(mx, x1);
    if (c + 2 < ml) mx = fmaxf(mx, x2);
    if (c + 3 < ml) mx = fmaxf(mx, x3);
    mx = blockMax(mx, sh);
    float e0 = (c + 0 < ml) ? expf(x0 - mx) : 0.f;
    float e1 = (c + 1 < ml) ? expf(x1 - mx) : 0.f;
    float e2 = (c + 2 < ml) ? expf(x2 - mx) : 0.f;
    float e3 = (c + 3 < ml) ? expf(x3 - mx) : 0.f;
    float sum = blockSum(e0 + e1 + e2 + e3, sh);
    float is = 1.f / sum;
    float4 o = make_float4(e0 * is, e1 * is, e2 * is, e3 * is);
    *reinterpret_cast<float4*>(pattn + ((long)t * kB + b) * kS + c) = o;
    __half2* oh = reinterpret_cast<__half2*>(avh + row * kS + c);
    oh[0] = __floats2half2_rn(o.x, o.y);
    oh[1] = __floats2half2_rn(o.z, o.w);
}

// out = (1-hg)*tanh(LN(h1)+LN(h2)) + hg*prev
__global__ void final_kernel(const float* __restrict__ h1, const float* __restrict__ h2,
                             const float* __restrict__ HG, const float* __restrict__ prev,
                             const float* __restrict__ g_h, const float* __restrict__ b_h,
                             const float* __restrict__ g_c, const float* __restrict__ b_c,
                             float* __restrict__ out)
{
    __shared__ float sh[32];
    long row = blockIdx.x;
    int c = threadIdx.x * 4;
    float4 a = *reinterpret_cast<const float4*>(h1 + row * kD + c);
    float4 d = *reinterpret_cast<const float4*>(h2 + row * kD + c);
    float s1 = a.x + a.y + a.z + a.w;
    float q1 = a.x * a.x + a.y * a.y + a.z * a.z + a.w * a.w;
    float s2 = d.x + d.y + d.z + d.w;
    float q2 = d.x * d.x + d.y * d.y + d.z * d.z + d.w * d.w;
    s1 = blockSum(s1, sh);
    q1 = blockSum(q1, sh);
    s2 = blockSum(s2, sh);
    q2 = blockSum(q2, sh);
    const float invW = 1.f / kD;
    float m1 = s1 * invW, r1 = rsqrtf(q1 * invW - m1 * m1 + kEPS);
    float m2 = s2 * invW, r2 = rsqrtf(q2 * invW - m2 * m2 + kEPS);
    float4 hg = *reinterpret_cast<const float4*>(HG + row * kD + c);
    float4 pv = *reinterpret_cast<const float4*>(prev + row * kD + c);
    float t0 = tanhf(g_h[c + 0] * ((a.x - m1) * r1) + b_h[c + 0] +
                     g_c[c + 0] * ((d.x - m2) * r2) + b_c[c + 0]);
    float t1 = tanhf(g_h[c + 1] * ((a.y - m1) * r1) + b_h[c + 1] +
                     g_c[c + 1] * ((d.y - m2) * r2) + b_c[c + 1]);
    float t2 = tanhf(g_h[c + 2] * ((a.z - m1) * r1) + b_h[c + 2] +
                     g_c[c + 2] * ((d.z - m2) * r2) + b_c[c + 2]);
    float t3 = tanhf(g_h[c + 3] * ((a.w - m1) * r1) + b_h[c + 3] +
                     g_c[c + 3] * ((d.w - m2) * r2) + b_c[c + 3]);
    float4 o;
    o.x = (1.f - hg.x) * t0 + hg.x * pv.x;
    o.y = (1.f - hg.y) * t1 + hg.y * pv.y;
    o.z = (1.f - hg.z) * t2 + hg.z * pv.z;
    o.w = (1.f - hg.w) * t3 + hg.w * pv.w;
    *reinterpret_cast<float4*>(out + row * kD + c) = o;
}

// ---------------------------------------------------------------------------
// Launch
// ---------------------------------------------------------------------------
extern "C" void kernel_launch(void* const* d_in, const int* in_sizes, int n_in,
                              void* d_out, int out_size)
{
    int i_prev = -1, i_enc = -1, i_hidden = -1, i_ml = -1, i_Win = -1;
    int w4[4] = {-1, -1, -1, -1}; int n4 = 0;
    int p2[2] = {-1, -1};         int np = 0;
    int v8[8] = {-1, -1, -1, -1, -1, -1, -1, -1}; int nv = 0;
    for (int i = 0; i < n_in; i++) {
        switch (in_sizes[i]) {
            case 8388608: if (i_prev < 0) i_prev = i; else i_enc = i; break;
            case 16384:   i_hidden = i; break;
            case 32:      i_ml = i; break;
            case 786432:  i_Win = i; break;
            case 262144:  if (n4 < 4) w4[n4++] = i; break;
            case 1536:    if (np < 2) p2[np++] = i; break;
            case 512:     if (nv < 8) v8[nv++] = i; break;
            default: break;
        }
    }
    const float* prev   = (const float*)d_in[i_prev];
    const float* hidden = (const float*)d_in[i_hidden];
    const float* enc    = (const float*)d_in[i_enc];
    const int*   mlen   = (const int*)d_in[i_ml];
    const float* W_in   = (const float*)d_in[i_Win];
    const float* W_enc  = (const float*)d_in[w4[0]];
    const float* W_att  = (const float*)d_in[w4[1]];
    const float* W_hid  = (const float*)d_in[w4[2]];
    const float* W_ctx  = (const float*)d_in[w4[3]];
    const float* g_pre  = (const float*)d_in[p2[0]];
    const float* b_pre  = (const float*)d_in[p2[1]];
    const float* g_enc  = (const float*)d_in[v8[0]];
    const float* b_enc  = (const float*)d_in[v8[1]];
    const float* g_att  = (const float*)d_in[v8[2]];
    const float* b_att  = (const float*)d_in[v8[3]];
    const float* g_h    = (const float*)d_in[v8[4]];
    const float* b_h    = (const float*)d_in[v8[5]];
    const float* g_c    = (const float*)d_in[v8[6]];
    const float* b_c    = (const float*)d_in[v8[7]];

    float* sf = nullptr;
    __half* sh = nullptr;
    cudaGetSymbolAddress((void**)&sf, g_scf);
    cudaGetSymbolAddress((void**)&sh, g_sch);

    float* out       = (float*)d_out;            // [T,B,D]
    float* out_hid   = out + kTBD;               // [B,D]
    float* out_pattn = out_hid + (long)kB * kD;  // [T,B,S]

    cudaFuncSetAttribute(gemm_h_kernel<float>,
                         cudaFuncAttributeMaxDynamicSharedMemorySize, GEMM_SMEM);
    cudaFuncSetAttribute(gemm_h_kernel<__half>,
                         cudaFuncAttributeMaxDynamicSharedMemorySize, GEMM_SMEM);

    dim3 tb(32, 8);
    const float invsq = rsqrtf((float)kD);
    const long bDS = (long)kB * kD;

    cudaStream_t s1;
    cudaStreamCreateWithFlags(&s1, cudaStreamNonBlocking);
    cudaEvent_t eW, eP, eS, eH;
    cudaEventCreateWithFlags(&eW, cudaEventDisableTiming);
    cudaEventCreateWithFlags(&eP, cudaEventDisableTiming);
    cudaEventCreateWithFlags(&eS, cudaEventDisableTiming);
    cudaEventCreateWithFlags(&eH, cudaEventDisableTiming);

    // -- side stream: enc convert (independent of weights) --
    f2h_kernel<<<8192, 256, 0, s1>>>(enc, sh + HF_ENC, kTBD / 4);

    // -- main: prev convert + weight transposes (fp32 -> K-major fp16) --
    f2h_kernel<<<8192, 256>>>(prev, sh + HF_PREV, kTBD / 4);
    transpose_f2h_kernel<<<dim3(16, 16, 3), tb>>>(W_in, sh + HF_WTIN, kD, 3 * kD,
                                                  512, (long)kD * kD);
    transpose4_f2h_kernel<<<dim3(16, 16, 4), tb>>>(W_enc, W_att, W_hid, W_ctx,
                                                   sh + HF_WTENC, sh + HF_WTATT,
                                                   sh + HF_WTHID, sh + HF_WTCTX);
    cudaEventRecord(eW, 0);

    // -- side stream: enc chain --
    cudaStreamWaitEvent(s1, eW, 0);
    gemm_h_kernel<float><<<dim3(4, 128, 1), 256, GEMM_SMEM, s1>>>(
        sh + HF_ENC, sh + HF_WTENC, sf + OF_PCTX32, 512, 512, 512, 512, 0, 0, 0, 1.f);
    ln512h_kernel<<<(unsigned)kTB, 128, 0, s1>>>(sf + OF_PCTX32, sh + HF_PCTX,
                                                 g_enc, b_enc);
    transpose_h2h_kernel<<<dim3(16, 16, 32), tb, 0, s1>>>(
        sh + HF_PCTX, sh + HF_PCTXT, kS, kD, (long)kS * kD, (long)kD * kS);
    cudaEventRecord(eP, s1);

    // -- main: preact chain --
    gemm_h_kernel<float><<<dim3(12, 128, 1), 256, GEMM_SMEM>>>(
        sh + HF_PREV, sh + HF_WTIN, sf + OF_PRE, 512, 512, 512, 1536, 0, 0, 0, 1.f);
    ln_preact_kernel<<<(unsigned)kTB, 384>>>(sf + OF_PRE, g_pre, b_pre,
                                             sf + OF_Z, sf + OF_HG, sf + OF_PL);
    scan_kernel<<<(kB * kD) / 128, 128>>>(sf + OF_Z, sf + OF_PL, hidden,
                                          sh + HF_SS, sf + OF_SSL);
    cudaEventRecord(eS, 0);
    gemm_h_kernel<float><<<dim3(4, 128, 1), 256, GEMM_SMEM>>>(
        sh + HF_SS, sh + HF_WTATT, sf + OF_ATT32, 512, 512, 512, 512, 0, 0, 0, 1.f);
    ln512h_kernel<<<(unsigned)kTB, 128>>>(sf + OF_ATT32, sh + HF_ATT, g_att, b_att);

    // -- side stream: h1 = ss @ W_hidden --
    cudaStreamWaitEvent(s1, eS, 0);
    gemm_h_kernel<float><<<dim3(4, 128, 1), 256, GEMM_SMEM, s1>>>(
        sh + HF_SS, sh + HF_WTHID, sf + OF_H1, 512, 512, 512, 512, 0, 0, 0, 1.f);
    cudaEventRecord(eH, s1);

    // -- main: attention chain --
    cudaStreamWaitEvent(0, eP, 0);
    gemm_h_kernel<float><<<dim3(4, 4, 32), 256, GEMM_SMEM>>>(
        sh + HF_ATT, sh + HF_PCTX, sf + OF_AV32, 512,
        bDS, 512, 512, kD, (long)kS * kD, (long)kT * kS, 1.f);
    softmax_kernel<<<(unsigned)(kB * kT), 128>>>(sf + OF_AV32, sh + HF_AV,
                                                 out_pattn, mlen);
    gemm_h_kernel<__half><<<dim3(4, 4, 32), 256, GEMM_SMEM>>>(
        sh + HF_AV, sh + HF_PCTXT, sh + HF_AO, 512,
        512, 512, bDS, (long)kT * kS, (long)kD * kS, kD, invsq);
    gemm_h_kernel<float><<<dim3(4, 128, 1), 256, GEMM_SMEM>>>(
        sh + HF_AO, sh + HF_WTCTX, sf + OF_H2, 512, 512, 512, 512, 0, 0, 0, 1.f);

    // join h1, final blend
    cudaStreamWaitEvent(0, eH, 0);
    final_kernel<<<(unsigned)kTB, 128>>>(sf + OF_H1, sf + OF_H2, sf + OF_HG, prev,
                                         g_h, b_h, g_c, b_c, out);
    cudaMemcpyAsync(out_hid, sf + OF_SSL, (size_t)kB * kD * sizeof(float),
                    cudaMemcpyDeviceToDevice, 0);
    // (stream/events intentionally leaked: destroying mid-capture invalidates it)
}

// round 11
// speedup vs baseline: 2.1447x; 1.0098x over previous
#include <cuda_runtime.h>
#include <cuda_fp16.h>
#include <math.h>
#include <stdint.h>

// ---------------------------------------------------------------------------
// AttSRU: T=512, B=32, S=512, D=512, fp32 I/O.
// Round 11: fp16 mma GEMMs + all-fp16 intermediates (fp32 math inside
// LN/softmax/scan). Final outputs remain fp32.
// ---------------------------------------------------------------------------

namespace {
constexpr int  kT = 512, kB = 32, kS = 512, kD = 512;
constexpr long kTB   = (long)kT * kB;      // 16384 rows
constexpr long kTBD  = kTB * kD;           // 8388608
constexpr float kEPS = 1e-6f;

// fp16 scratch offsets (halfs)
constexpr long HF_PREV  = 0;
constexpr long HF_ENC   = HF_PREV  + kTBD;
constexpr long HF_PCTXR = HF_ENC   + kTBD;   // enc GEMM raw out
constexpr long HF_PCTX  = HF_PCTXR + kTBD;   // LN'd
constexpr long HF_PCTXT = HF_PCTX  + kTBD;   // [B,D,S]
constexpr long HF_SS    = HF_PCTXT + kTBD;
constexpr long HF_ATTR  = HF_SS    + kTBD;   // attn GEMM raw out
constexpr long HF_ATT   = HF_ATTR  + kTBD;   // LN'd
constexpr long HF_SC    = HF_ATT   + kTBD;   // align scores [B,T,S]
constexpr long HF_AV    = HF_SC    + kTBD;   // softmax probs
constexpr long HF_AO    = HF_AV    + kTBD;   // attn_out
constexpr long HF_H1    = HF_AO    + kTBD;
constexpr long HF_H2    = HF_H1    + kTBD;
constexpr long HF_Z     = HF_H2    + kTBD;
constexpr long HF_HG    = HF_Z     + kTBD;
constexpr long HF_PL    = HF_HG    + kTBD;
constexpr long HF_PRE   = HF_PL    + kTBD;   // [TB,3D]
constexpr long HF_WTIN  = HF_PRE   + 3 * kTBD;
constexpr long HF_WTENC = HF_WTIN  + (long)3 * kD * kD;
constexpr long HF_WTATT = HF_WTENC + (long)kD * kD;
constexpr long HF_WTHID = HF_WTATT + (long)kD * kD;
constexpr long HF_WTCTX = HF_WTHID + (long)kD * kD;
constexpr long kSCH     = HF_WTCTX + (long)kD * kD;

// fp32 scratch: final scan state only
constexpr long kSCF = (long)kB * kD;

// fp16 GEMM smem: K-chunk 32 halfs/row, row stride 40 halfs (80B)
constexpr int RSH = 40;
constexpr int OPH = 128 * RSH;
constexpr int STG = 2 * OPH;
constexpr int GEMM_SMEM = 3 * STG * 2;        // 61440 B -> 2 CTAs/SM
}

__device__ float  g_scf[kSCF];
__device__ __half g_sch[kSCH];

// ---------------------------------------------------------------------------
// Helpers
// ---------------------------------------------------------------------------
__device__ __forceinline__ float warpSum(float v) {
#pragma unroll
    for (int o = 16; o; o >>= 1) v += __shfl_xor_sync(0xffffffffu, v, o);
    return v;
}
__device__ __forceinline__ float warpMax(float v) {
#pragma unroll
    for (int o = 16; o; o >>= 1) v = fmaxf(v, __shfl_xor_sync(0xffffffffu, v, o));
    return v;
}
__device__ __forceinline__ float blockSum(float v, float* sh) {
    int w = threadIdx.x >> 5, l = threadIdx.x & 31, nw = blockDim.x >> 5;
    v = warpSum(v);
    if (l == 0) sh[w] = v;
    __syncthreads();
    v = (l < nw) ? sh[l] : 0.f;
    v = warpSum(v);
    __syncthreads();
    return v;
}
__device__ __forceinline__ float blockMax(float v, float* sh) {
    int w = threadIdx.x >> 5, l = threadIdx.x & 31, nw = blockDim.x >> 5;
    v = warpMax(v);
    if (l == 0) sh[w] = v;
    __syncthreads();
    v = (l < nw) ? sh[l] : -INFINITY;
    v = warpMax(v);
    __syncthreads();
    return v;
}
__device__ __forceinline__ float sigm(float x) { return 1.f / (1.f + expf(-x)); }

// load 4 consecutive halfs -> 4 floats
__device__ __forceinline__ void ld4h(const __half* p, float& a, float& b,
                                     float& c, float& d) {
    uint2 r = *reinterpret_cast<const uint2*>(p);
    __half2 h0 = *reinterpret_cast<__half2*>(&r.x);
    __half2 h1 = *reinterpret_cast<__half2*>(&r.y);
    float2 f0 = __half22float2(h0), f1 = __half22float2(h1);
    a = f0.x; b = f0.y; c = f1.x; d = f1.y;
}
// store 4 floats -> 4 consecutive halfs
__device__ __forceinline__ void st4h(__half* p, float a, float b, float c, float d) {
    uint2 r;
    __half2 h0 = __floats2half2_rn(a, b), h1 = __floats2half2_rn(c, d);
    r.x = *reinterpret_cast<uint32_t*>(&h0);
    r.y = *reinterpret_cast<uint32_t*>(&h1);
    *reinterpret_cast<uint2*>(p) = r;
}

__device__ __forceinline__ void ldsm4(uint32_t& r0, uint32_t& r1,
                                      uint32_t& r2, uint32_t& r3, uint32_t addr) {
    asm volatile("ldmatrix.sync.aligned.m8n8.x4.shared.b16 {%0,%1,%2,%3}, [%4];"
                 : "=r"(r0), "=r"(r1), "=r"(r2), "=r"(r3) : "r"(addr));
}

// ---------------------------------------------------------------------------
// fp16 mma GEMM: C[M,N] = alpha * A[M,K] @ B[N,K]^T  (fp32 accum, fp16 out)
// Grid: (N/128, M/128, batch). Block: 256 (8 warps 4x2, warp tile 32x64).
// ---------------------------------------------------------------------------
__global__ __launch_bounds__(256, 2)
void gemm_h_kernel(const __half* __restrict__ A, const __half* __restrict__ B,
                   __half* __restrict__ C, int K,
                   long lda, long ldb, long ldc,
                   long sA, long sB, long sC, float alpha)
{
    extern __shared__ __half smh[];
    const uint32_t sb = (uint32_t)__cvta_generic_to_shared(smh);
    A += (long)blockIdx.z * sA;
    B += (long)blockIdx.z * sB;
    C += (long)blockIdx.z * sC;
    const int bm = blockIdx.y * 128, bn = blockIdx.x * 128;
    const int tid = threadIdx.x, wid = tid >> 5, lane = tid & 31;
    const int mw = (wid >> 1) * 32, nw = (wid & 1) * 64;
    const int lr = lane >> 2, lc = lane & 3;

    const int aoff = (mw + (lane & 15)) * RSH + (lane >> 4) * 8;
    const int boff0 = OPH + (nw + (lane & 7) + (lane >> 4) * 8) * RSH
                    + ((lane >> 3) & 1) * 8;

    const __half* gp[4];
    uint32_t dsto[4];
#pragma unroll
    for (int i = 0; i < 4; i++) {
        int id = tid + i * 256;
        bool isA = id < 512;
        int rid = id & 511;
        int row = rid >> 2, q = rid & 3;
        gp[i] = (isA ? A + (long)(bm + row) * lda
                     : B + (long)(bn + row) * ldb) + q * 8;
        dsto[i] = (isA ? 0u : (uint32_t)OPH) + (uint32_t)(row * RSH + q * 8);
    }
    const int nch = K >> 5;

    auto load_chunk = [&](int c, int s) {
        long ko = (long)c * 32;
        uint32_t base = (uint32_t)(s * STG);
#pragma unroll
        for (int i = 0; i < 4; i++) {
            uint32_t d = sb + (base + dsto[i]) * 2u;
            asm volatile("cp.async.cg.shared.global [%0], [%1], 16;"
                         :: "r"(d), "l"(gp[i] + ko));
        }
    };

    float acc[2][8][4];
#pragma unroll
    for (int i = 0; i < 2; i++)
#pragma unroll
        for (int j = 0; j < 8; j++)
#pragma unroll
            for (int v = 0; v < 4; v++) acc[i][j][v] = 0.f;

    load_chunk(0, 0);
    asm volatile("cp.async.commit_group;");
    if (nch > 1) {
        load_chunk(1, 1);
        asm volatile("cp.async.commit_group;");
    }

    for (int c = 0; c < nch; c++) {
        if (c + 1 < nch) asm volatile("cp.async.wait_group 1;");
        else             asm volatile("cp.async.wait_group 0;");
        __syncthreads();
        if (c + 2 < nch) {
            load_chunk(c + 2, (c + 2) % 3);
            asm volatile("cp.async.commit_group;");
        }
        const uint32_t stb = sb + (uint32_t)((c % 3) * STG) * 2u;
#pragma unroll
        for (int ks = 0; ks < 2; ks++) {
            const uint32_t kb = (uint32_t)(ks * 16) * 2u;
            uint32_t a[2][4];
#pragma unroll
            for (int im = 0; im < 2; im++)
                ldsm4(a[im][0], a[im][1], a[im][2], a[im][3],
                      stb + (uint32_t)(aoff + im * 16 * RSH) * 2u + kb);
#pragma unroll
            for (int p = 0; p < 4; p++) {
                uint32_t b0, b1, b2, b3;
                ldsm4(b0, b1, b2, b3, stb + (uint32_t)(boff0 + p * 16 * RSH) * 2u + kb);
#pragma unroll
                for (int im = 0; im < 2; im++) {
                    asm volatile(
                        "mma.sync.aligned.m16n8k16.row.col.f32.f16.f16.f32 "
                        "{%0,%1,%2,%3}, {%4,%5,%6,%7}, {%8,%9}, {%0,%1,%2,%3};"
                        : "+f"(acc[im][2 * p][0]), "+f"(acc[im][2 * p][1]),
                          "+f"(acc[im][2 * p][2]), "+f"(acc[im][2 * p][3])
                        : "r"(a[im][0]), "r"(a[im][1]), "r"(a[im][2]), "r"(a[im][3]),
                          "r"(b0), "r"(b1));
                    asm volatile(
                        "mma.sync.aligned.m16n8k16.row.col.f32.f16.f16.f32 "
                        "{%0,%1,%2,%3}, {%4,%5,%6,%7}, {%8,%9}, {%0,%1,%2,%3};"
                        : "+f"(acc[im][2 * p + 1][0]), "+f"(acc[im][2 * p + 1][1]),
                          "+f"(acc[im][2 * p + 1][2]), "+f"(acc[im][2 * p + 1][3])
                        : "r"(a[im][0]), "r"(a[im][1]), "r"(a[im][2]), "r"(a[im][3]),
                          "r"(b2), "r"(b3));
                }
            }
        }
    }

#pragma unroll
    for (int im = 0; im < 2; im++) {
        long r0 = (long)(bm + mw + im * 16 + lr);
#pragma unroll
        for (int jn = 0; jn < 8; jn++) {
            long col = bn + nw + jn * 8 + lc * 2;
            *reinterpret_cast<__half2*>(C + r0 * ldc + col) =
                __floats2half2_rn(acc[im][jn][0] * alpha, acc[im][jn][1] * alpha);
            *reinterpret_cast<__half2*>(C + (r0 + 8) * ldc + col) =
                __floats2half2_rn(acc[im][jn][2] * alpha, acc[im][jn][3] * alpha);
        }
    }
}

// ---------------------------------------------------------------------------
// fp32 -> fp16 convert
// ---------------------------------------------------------------------------
__global__ void f2h_kernel(const float* __restrict__ in, __half* __restrict__ out,
                           long n4)
{
    long i = (long)blockIdx.x * blockDim.x + threadIdx.x;
    if (i >= n4) return;
    float4 v = reinterpret_cast<const float4*>(in)[i];
    reinterpret_cast<__half2*>(out)[i * 2]     = __floats2half2_rn(v.x, v.y);
    reinterpret_cast<__half2*>(out)[i * 2 + 1] = __floats2half2_rn(v.z, v.w);
}

// ---------------------------------------------------------------------------
// Transposes
// ---------------------------------------------------------------------------
__global__ void transpose_f2h_kernel(const float* __restrict__ in,
                                     __half* __restrict__ out,
                                     int R, int C, long sIn, long sOut)
{
    __shared__ float t[32][33];
    in  += (long)blockIdx.z * sIn;
    out += (long)blockIdx.z * sOut;
    int bx = blockIdx.x * 32, by = blockIdx.y * 32;
    int x = threadIdx.x, y = threadIdx.y;
#pragma unroll
    for (int i = 0; i < 32; i += 8) t[y + i][x] = in[(long)(by + y + i) * C + bx + x];
    __syncthreads();
#pragma unroll
    for (int i = 0; i < 32; i += 8)
        out[(long)(bx + y + i) * R + by + x] = __float2half_rn(t[x][y + i]);
}

__global__ void transpose4_f2h_kernel(const float* __restrict__ w0, const float* __restrict__ w1,
                                      const float* __restrict__ w2, const float* __restrict__ w3,
                                      __half* __restrict__ o0, __half* __restrict__ o1,
                                      __half* __restrict__ o2, __half* __restrict__ o3)
{
    __shared__ float t[32][33];
    const float* in; __half* out;
    switch (blockIdx.z) {
        case 0: in = w0; out = o0; break;
        case 1: in = w1; out = o1; break;
        case 2: in = w2; out = o2; break;
        default: in = w3; out = o3; break;
    }
    int bx = blockIdx.x * 32, by = blockIdx.y * 32;
    int x = threadIdx.x, y = threadIdx.y;
#pragma unroll
    for (int i = 0; i < 32; i += 8) t[y + i][x] = in[(long)(by + y + i) * kD + bx + x];
    __syncthreads();
#pragma unroll
    for (int i = 0; i < 32; i += 8)
        out[(long)(bx + y + i) * kD + by + x] = __float2half_rn(t[x][y + i]);
}

__global__ void transpose_h2h_kernel(const __half* __restrict__ in,
                                     __half* __restrict__ out,
                                     int R, int C, long sIn, long sOut)
{
    __shared__ __half t[32][34];
    in  += (long)blockIdx.z * sIn;
    out += (long)blockIdx.z * sOut;
    int bx = blockIdx.x * 32, by = blockIdx.y * 32;
    int x = threadIdx.x, y = threadIdx.y;
#pragma unroll
    for (int i = 0; i < 32; i += 8) t[y + i][x] = in[(long)(by + y + i) * C + bx + x];
    __syncthreads();
#pragma unroll
    for (int i = 0; i < 32; i += 8)
        out[(long)(bx + y + i) * R + by + x] = t[x][y + i];
}

// ---------------------------------------------------------------------------
// LN over 3D=1536 (fp16 in), split + sigmoid -> fp16 Z / HG / PL. block=384.
// ---------------------------------------------------------------------------
__global__ void ln_preact_kernel(const __half* __restrict__ pre,
                                 const float* __restrict__ g, const float* __restrict__ bb,
                                 __half* __restrict__ Z, __half* __restrict__ HG,
                                 __half* __restrict__ PL)
{
    __shared__ float sh[32];
    long row = blockIdx.x;
    int c = threadIdx.x * 4;
    float vx, vy, vz, vw;
    ld4h(pre + row * (3 * kD) + c, vx, vy, vz, vw);
    float s = vx + vy + vz + vw;
    float q = vx * vx + vy * vy + vz * vz + vw * vw;
    s = blockSum(s, sh);
    q = blockSum(q, sh);
    const float invW = 1.f / (3 * kD);
    float m  = s * invW;
    float rv = rsqrtf(q * invW - m * m + kEPS);
    float n0 = g[c + 0] * ((vx - m) * rv) + bb[c + 0];
    float n1 = g[c + 1] * ((vy - m) * rv) + bb[c + 1];
    float n2 = g[c + 2] * ((vz - m) * rv) + bb[c + 2];
    float n3 = g[c + 3] * ((vw - m) * rv) + bb[c + 3];
    long rD = row * kD;
    if (c < kD) {
        st4h(Z + rD + c, sigm(n0), sigm(n1), sigm(n2), sigm(n3));
    } else if (c < 2 * kD) {
        st4h(HG + rD + (c - kD), sigm(n0), sigm(n1), sigm(n2), sigm(n3));
    } else {
        st4h(PL + rD + (c - 2 * kD), n0, n1, n2, n3);
    }
}

// LN over D=512: fp16 in -> fp16 out. block=128, grid=rows.
__global__ void ln512h_kernel(const __half* __restrict__ x, __half* __restrict__ out,
                              const float* __restrict__ g, const float* __restrict__ b)
{
    __shared__ float sh[32];
    long row = blockIdx.x;
    int c = threadIdx.x * 4;
    float vx, vy, vz, vw;
    ld4h(x + row * kD + c, vx, vy, vz, vw);
    float s = vx + vy + vz + vw;
    float q = vx * vx + vy * vy + vz * vz + vw * vw;
    s = blockSum(s, sh);
    q = blockSum(q, sh);
    const float invW = 1.f / kD;
    float m  = s * invW;
    float rv = rsqrtf(q * invW - m * m + kEPS);
    st4h(out + row * kD + c,
         g[c + 0] * ((vx - m) * rv) + b[c + 0],
         g[c + 1] * ((vy - m) * rv) + b[c + 1],
         g[c + 2] * ((vz - m) * rv) + b[c + 2],
         g[c + 3] * ((vw - m) * rv) + b[c + 3]);
}

// SRU scan over half2 lanes: fp32 state, fp16 ss out, fp32 final state.
__global__ __launch_bounds__(64)
void scan_kernel(const __half2* __restrict__ Z, const __half2* __restrict__ PL,
                 const float* __restrict__ h0, __half2* __restrict__ ssh,
                 float* __restrict__ sslast)
{
    constexpr int BATCH = 16;
    int idx = blockIdx.x * 64 + threadIdx.x;           // pair index 0..8191
    float2 s = reinterpret_cast<const float2*>(h0)[idx];
    const long stride = (long)kB * kD / 2;
    long off = idx;
    for (int g = 0; g < kT / BATCH; g++) {
        __half2 z[BATCH], p[BATCH];
#pragma unroll
        for (int j = 0; j < BATCH; j++) z[j] = Z[off + j * stride];
#pragma unroll
        for (int j = 0; j < BATCH; j++) p[j] = PL[off + j * stride];
#pragma unroll
        for (int j = 0; j < BATCH; j++) {
            float2 zf = __half22float2(z[j]);
            float2 pf = __half22float2(p[j]);
            s.x = (1.f - zf.x) * s.x + zf.x * pf.x;
            s.y = (1.f - zf.y) * s.y + zf.y * pf.y;
            ssh[off + j * stride] = __floats2half2_rn(s.x, s.y);
        }
        off += (long)BATCH * stride;
    }
    reinterpret_cast<float2*>(sslast)[idx] = s;
}

// Masked softmax over S=512: fp16 scores in; fp32 p_attn out + fp16 probs.
__global__ void softmax_kernel(const __half* __restrict__ sc, __half* __restrict__ avh,
                               float* __restrict__ pattn, const int* __restrict__ mlen)
{
    __shared__ float sh[32];
    long row = blockIdx.x;                 // b*T + t
    int b = (int)(row / kT), t = (int)(row % kT);
    int ml = mlen[b];
    int c = threadIdx.x * 4;
    float x0, x1, x2, x3;
    ld4h(sc + row * kS + c, x0, x1, x2, x3);
    const float inv = rsqrtf((float)kD);
    x0 *= inv; x1 *= inv; x2 *= inv; x3 *= inv;
    float mx = -INFINITY;
    if (c + 0 < ml) mx = fmaxf(mx, x0);
    if (c + 1 < ml) mx = fmaxf(mx, x1);
    if (c + 2 < ml) mx = fmaxf(mx, x2);
    if (c + 3 < ml) mx = fmaxf(mx, x3);
    mx = blockMax(mx, sh);
    float e0 = (c + 0 < ml) ? expf(x0 - mx) : 0.f;
    float e1 = (c + 1 < ml) ? expf(x1 - mx) : 0.f;
    float e2 = (c + 2 < ml) ? expf(x2 - mx) : 0.f;
    float e3 = (c + 3 < ml) ? expf(x3 - mx) : 0.f;
    float sum = blockSum(e0 + e1 + e2 + e3, sh);
    float is = 1.f / sum;
    float4 o = make_float4(e0 * is, e1 * is, e2 * is, e3 * is);
    *reinterpret_cast<float4*>(pattn + ((long)t * kB + b) * kS + c) = o;
    st4h(avh + row * kS + c, o.x, o.y, o.z, o.w);
}

// out = (1-hg)*tanh(LN(h1)+LN(h2)) + hg*prev   (h1,h2,HG fp16; prev,out fp32)
__global__ void final_kernel(const __half* __restrict__ h1, const __half* __restrict__ h2,
                             const __half* __restrict__ HG, const float* __restrict__ prev,
                             const float* __restrict__ g_h, const float* __restrict__ b_h,
                             const float* __restrict__ g_c, const float* __restrict__ b_c,
                             float* __restrict__ out)
{
    __shared__ float sh[32];
    long row = blockIdx.x;
    int c = threadIdx.x * 4;
    float ax, ay, az, aw, dx, dy, dz, dw;
    ld4h(h1 + row * kD + c, ax, ay, az, aw);
    ld4h(h2 + row * kD + c, dx, dy, dz, dw);
    float s1 = ax + ay + az + aw;
    float q1 = ax * ax + ay * ay + az * az + aw * aw;
    float s2 = dx + dy + dz + dw;
    float q2 = dx * dx + dy * dy + dz * dz + dw * dw;
    s1 = blockSum(s1, sh);
    q1 = blockSum(q1, sh);
    s2 = blockSum(s2, sh);
    q2 = blockSum(q2, sh);
    const float invW = 1.f / kD;
    float m1 = s1 * invW, r1 = rsqrtf(q1 * invW - m1 * m1 + kEPS);
    float m2 = s2 * invW, r2 = rsqrtf(q2 * invW - m2 * m2 + kEPS);
    float h0, h1v, h2v, h3;
    ld4h(HG + row * kD + c, h0, h1v, h2v, h3);
    float4 pv = *reinterpret_cast<const float4*>(prev + row * kD + c);
    float t0 = tanhf(g_h[c + 0] * ((ax - m1) * r1) + b_h[c + 0] +
                     g_c[c + 0] * ((dx - m2) * r2) + b_c[c + 0]);
    float t1 = tanhf(g_h[c + 1] * ((ay - m1) * r1) + b_h[c + 1] +
                     g_c[c + 1] * ((dy - m2) * r2) + b_c[c + 1]);
    float t2 = tanhf(g_h[c + 2] * ((az - m1) * r1) + b_h[c + 2] +
                     g_c[c + 2] * ((dz - m2) * r2) + b_c[c + 2]);
    float t3 = tanhf(g_h[c + 3] * ((aw - m1) * r1) + b_h[c + 3] +
                     g_c[c + 3] * ((dw - m2) * r2) + b_c[c + 3]);
    float4 o;
    o.x = (1.f - h0)  * t0 + h0  * pv.x;
    o.y = (1.f - h1v) * t1 + h1v * pv.y;
    o.z = (1.f - h2v) * t2 + h2v * pv.z;
    o.w = (1.f - h3)  * t3 + h3  * pv.w;
    *reinterpret_cast<float4*>(out + row * kD + c) = o;
}

// ---------------------------------------------------------------------------
// Launch
// ---------------------------------------------------------------------------
extern "C" void kernel_launch(void* const* d_in, const int* in_sizes, int n_in,
                              void* d_out, int out_size)
{
    int i_prev = -1, i_enc = -1, i_hidden = -1, i_ml = -1, i_Win = -1;
    int w4[4] = {-1, -1, -1, -1}; int n4 = 0;
    int p2[2] = {-1, -1};         int np = 0;
    int v8[8] = {-1, -1, -1, -1, -1, -1, -1, -1}; int nv = 0;
    for (int i = 0; i < n_in; i++) {
        switch (in_sizes[i]) {
            case 8388608: if (i_prev < 0) i_prev = i; else i_enc = i; break;
            case 16384:   i_hidden = i; break;
            case 32:      i_ml = i; break;
            case 786432:  i_Win = i; break;
            case 262144:  if (n4 < 4) w4[n4++] = i; break;
            case 1536:    if (np < 2) p2[np++] = i; break;
            case 512:     if (nv < 8) v8[nv++] = i; break;
            default: break;
        }
    }
    const float* prev   = (const float*)d_in[i_prev];
    const float* hidden = (const float*)d_in[i_hidden];
    const float* enc    = (const float*)d_in[i_enc];
    const int*   mlen   = (const int*)d_in[i_ml];
    const float* W_in   = (const float*)d_in[i_Win];
    const float* W_enc  = (const float*)d_in[w4[0]];
    const float* W_att  = (const float*)d_in[w4[1]];
    const float* W_hid  = (const float*)d_in[w4[2]];
    const float* W_ctx  = (const float*)d_in[w4[3]];
    const float* g_pre  = (const float*)d_in[p2[0]];
    const float* b_pre  = (const float*)d_in[p2[1]];
    const float* g_enc  = (const float*)d_in[v8[0]];
    const float* b_enc  = (const float*)d_in[v8[1]];
    const float* g_att  = (const float*)d_in[v8[2]];
    const float* b_att  = (const float*)d_in[v8[3]];
    const float* g_h    = (const float*)d_in[v8[4]];
    const float* b_h    = (const float*)d_in[v8[5]];
    const float* g_c    = (const float*)d_in[v8[6]];
    const float* b_c    = (const float*)d_in[v8[7]];

    float* sf = nullptr;
    __half* sh = nullptr;
    cudaGetSymbolAddress((void**)&sf, g_scf);
    cudaGetSymbolAddress((void**)&sh, g_sch);

    float* out       = (float*)d_out;            // [T,B,D]
    float* out_hid   = out + kTBD;               // [B,D]
    float* out_pattn = out_hid + (long)kB * kD;  // [T,B,S]

    cudaFuncSetAttribute(gemm_h_kernel,
                         cudaFuncAttributeMaxDynamicSharedMemorySize, GEMM_SMEM);

    dim3 tb(32, 8);
    const float invsq = rsqrtf((float)kD);
    const long bDS = (long)kB * kD;

    cudaStream_t s1;
    cudaStreamCreateWithFlags(&s1, cudaStreamNonBlocking);
    cudaEvent_t eW, eP, eS, eH;
    cudaEventCreateWithFlags(&eW, cudaEventDisableTiming);
    cudaEventCreateWithFlags(&eP, cudaEventDisableTiming);
    cudaEventCreateWithFlags(&eS, cudaEventDisableTiming);
    cudaEventCreateWithFlags(&eH, cudaEventDisableTiming);

    // -- side stream: enc convert --
    f2h_kernel<<<8192, 256, 0, s1>>>(enc, sh + HF_ENC, kTBD / 4);

    // -- main: prev convert + weight transposes --
    f2h_kernel<<<8192, 256>>>(prev, sh + HF_PREV, kTBD / 4);
    transpose_f2h_kernel<<<dim3(16, 16, 3), tb>>>(W_in, sh + HF_WTIN, kD, 3 * kD,
                                                  512, (long)kD * kD);
    transpose4_f2h_kernel<<<dim3(16, 16, 4), tb>>>(W_enc, W_att, W_hid, W_ctx,
                                                   sh + HF_WTENC, sh + HF_WTATT,
                                                   sh + HF_WTHID, sh + HF_WTCTX);
    cudaEventRecord(eW, 0);

    // -- side stream: enc chain --
    cudaStreamWaitEvent(s1, eW, 0);
    gemm_h_kernel<<<dim3(4, 128, 1), 256, GEMM_SMEM, s1>>>(
        sh + HF_ENC, sh + HF_WTENC, sh + HF_PCTXR, 512, 512, 512, 512, 0, 0, 0, 1.f);
    ln512h_kernel<<<(unsigned)kTB, 128, 0, s1>>>(sh + HF_PCTXR, sh + HF_PCTX,
                                                 g_enc, b_enc);
    transpose_h2h_kernel<<<dim3(16, 16, 32), tb, 0, s1>>>(
        sh + HF_PCTX, sh + HF_PCTXT, kS, kD, (long)kS * kD, (long)kD * kS);
    cudaEventRecord(eP, s1);

    // -- main: preact chain --
    gemm_h_kernel<<<dim3(12, 128, 1), 256, GEMM_SMEM>>>(
        sh + HF_PREV, sh + HF_WTIN, sh + HF_PRE, 512, 512, 512, 1536, 0, 0, 0, 1.f);
    ln_preact_kernel<<<(unsigned)kTB, 384>>>(sh + HF_PRE, g_pre, b_pre,
                                             sh + HF_Z, sh + HF_HG, sh + HF_PL);
    scan_kernel<<<128, 64>>>(reinterpret_cast<__half2*>(sh + HF_Z),
                             reinterpret_cast<__half2*>(sh + HF_PL), hidden,
                             reinterpret_cast<__half2*>(sh + HF_SS), sf);
    cudaEventRecord(eS, 0);
    gemm_h_kernel<<<dim3(4, 128, 1), 256, GEMM_SMEM>>>(
        sh + HF_SS, sh + HF_WTATT, sh + HF_ATTR, 512, 512, 512, 512, 0, 0, 0, 1.f);
    ln512h_kernel<<<(unsigned)kTB, 128>>>(sh + HF_ATTR, sh + HF_ATT, g_att, b_att);

    // -- side stream: h1 = ss @ W_hidden --
    cudaStreamWaitEvent(s1, eS, 0);
    gemm_h_kernel<<<dim3(4, 128, 1), 256, GEMM_SMEM, s1>>>(
        sh + HF_SS, sh + HF_WTHID, sh + HF_H1, 512, 512, 512, 512, 0, 0, 0, 1.f);
    cudaEventRecord(eH, s1);

    // -- main: attention chain --
    cudaStreamWaitEvent(0, eP, 0);
    gemm_h_kernel<<<dim3(4, 4, 32), 256, GEMM_SMEM>>>(
        sh + HF_ATT, sh + HF_PCTX, sh + HF_SC, 512,
        bDS, 512, 512, kD, (long)kS * kD, (long)kT * kS, 1.f);
    softmax_kernel<<<(unsigned)(kB * kT), 128>>>(sh + HF_SC, sh + HF_AV,
                                                 out_pattn, mlen);
    gemm_h_kernel<<<dim3(4, 4, 32), 256, GEMM_SMEM>>>(
        sh + HF_AV, sh + HF_PCTXT, sh + HF_AO, 512,
        512, 512, bDS, (long)kT * kS, (long)kD * kS, kD, invsq);
    gemm_h_kernel<<<dim3(4, 128, 1), 256, GEMM_SMEM>>>(
        sh + HF_AO, sh + HF_WTCTX, sh + HF_H2, 512, 512, 512, 512, 0, 0, 0, 1.f);

    // join h1, final blend
    cudaStreamWaitEvent(0, eH, 0);
    final_kernel<<<(unsigned)kTB, 128>>>(sh + HF_H1, sh + HF_H2, sh + HF_HG, prev,
                                         g_h, b_h, g_c, b_c, out);
    cudaMemcpyAsync(out_hid, sf, (size_t)kB * kD * sizeof(float),
                    cudaMemcpyDeviceToDevice, 0);
    // (stream/events intentionally leaked: destroying mid-capture invalidates it)
}